// round 2
// baseline (speedup 1.0000x reference)
#include <cuda_runtime.h>

#define T_WARM 48
#define OUT_STEPS 24
#define UNITS 32
#define NTHREADS 256

__device__ __forceinline__ float sigmoid_f(float x) {
    float e = __expf(-x);
    return __fdividef(1.0f, 1.0f + e);
}

__device__ __forceinline__ float tanh_f(float x) {
    float ax = fabsf(x);
    float e = __expf(-2.0f * ax);            // in (0, 1], no overflow
    float r = __fdividef(1.0f - e, 1.0f + e);
    return copysignf(r, x);
}

__global__ void __launch_bounds__(NTHREADS, 2)
feedback_lstm_kernel(const float* __restrict__ X,
                     const float* __restrict__ Wkw, const float* __restrict__ Ukw,
                     const float* __restrict__ bw,
                     const float* __restrict__ Wkd, const float* __restrict__ Ukd,
                     const float* __restrict__ bdv,
                     const float* __restrict__ Wd,  const float* __restrict__ bd,
                     float* __restrict__ out)
{
    // U stored transposed: sU[col*32 + k] = U[k*128 + col], col = gate*32 + unit.
    // At compute time every lane reads the same address -> broadcast, conflict-free,
    // and each gate's 32 k-values are contiguous -> float4 LDS.128.
    __shared__ float sUw[128 * 32];
    __shared__ float sUd[128 * 32];
    __shared__ float sWw[128], sbw[128], sWdk[128], sbd[128];
    __shared__ float sWo[UNITS];
    __shared__ float sbo;

    const int tid = threadIdx.x;
    #pragma unroll 4
    for (int i = tid; i < 128 * 32; i += NTHREADS) {
        int col = i >> 5, k = i & 31;
        sUw[i] = Ukw[k * 128 + col];
        sUd[i] = Ukd[k * 128 + col];
    }
    if (tid < 128) {
        sWw[tid]  = Wkw[tid];
        sbw[tid]  = bw[tid];
        sWdk[tid] = Wkd[tid];
        sbd[tid]  = bdv[tid];
    }
    if (tid < UNITS) sWo[tid] = Wd[tid];
    if (tid == 0) sbo = bd[0];
    __syncthreads();

    const int b = blockIdx.x * NTHREADS + tid;
    const float* xp = X + (size_t)b * T_WARM;
    float* op = out + (size_t)b * OUT_STEPS;

    float h[UNITS], c[UNITS];
    #pragma unroll
    for (int j = 0; j < UNITS; j++) { h[j] = 0.f; c[j] = 0.f; }

    float p = 0.f;
    const float bo = sbo;

    // Fused loop: t in [0,48) warmup, t in [48,71) decode. One copy of the
    // fully-unrolled cell body keeps the I$ footprint halved.
    for (int t = 0; t < T_WARM + OUT_STEPS - 1; t++) {
        const bool warm = (t < T_WARM);
        const float x = warm ? __ldg(xp + t) : p;
        const float* sU = warm ? sUw : sUd;
        const float* sW = warm ? sWw : sWdk;
        const float* sb = warm ? sbw : sbd;

        float hn[UNITS];
        #pragma unroll
        for (int j = 0; j < UNITS; j++) {
            float zi = fmaf(x, sW[j],      sb[j]);
            float zf = fmaf(x, sW[32 + j], sb[32 + j]);
            float zg = fmaf(x, sW[64 + j], sb[64 + j]);
            float zo = fmaf(x, sW[96 + j], sb[96 + j]);
            const float4* ui = (const float4*)(sU + j * 32);
            const float4* uf = (const float4*)(sU + (32 + j) * 32);
            const float4* ug = (const float4*)(sU + (64 + j) * 32);
            const float4* uo = (const float4*)(sU + (96 + j) * 32);
            #pragma unroll
            for (int k = 0; k < 8; k++) {
                float4 vi = ui[k], vf = uf[k], vg = ug[k], vo = uo[k];
                float h0 = h[4*k], h1 = h[4*k+1], h2 = h[4*k+2], h3 = h[4*k+3];
                zi = fmaf(h0, vi.x, zi); zi = fmaf(h1, vi.y, zi);
                zi = fmaf(h2, vi.z, zi); zi = fmaf(h3, vi.w, zi);
                zf = fmaf(h0, vf.x, zf); zf = fmaf(h1, vf.y, zf);
                zf = fmaf(h2, vf.z, zf); zf = fmaf(h3, vf.w, zf);
                zg = fmaf(h0, vg.x, zg); zg = fmaf(h1, vg.y, zg);
                zg = fmaf(h2, vg.z, zg); zg = fmaf(h3, vg.w, zg);
                zo = fmaf(h0, vo.x, zo); zo = fmaf(h1, vo.y, zo);
                zo = fmaf(h2, vo.z, zo); zo = fmaf(h3, vo.w, zo);
            }
            float ig = sigmoid_f(zi);
            float fg = sigmoid_f(zf);
            float gg = tanh_f(zg);
            float og = sigmoid_f(zo);
            float cn = fmaf(fg, c[j], ig * gg);
            c[j] = cn;
            hn[j] = og * tanh_f(cn);
        }
        #pragma unroll
        for (int j = 0; j < UNITS; j++) h[j] = hn[j];

        if (t >= T_WARM - 1) {
            float acc = bo;
            #pragma unroll
            for (int j = 0; j < UNITS; j++) acc = fmaf(h[j], sWo[j], acc);
            p = acc;
            op[t - (T_WARM - 1)] = p;
        }
    }
}

extern "C" void kernel_launch(void* const* d_in, const int* in_sizes, int n_in,
                              void* d_out, int out_size) {
    const float* X   = (const float*)d_in[0];
    const float* Wkw = (const float*)d_in[1];
    const float* Ukw = (const float*)d_in[2];
    const float* bw  = (const float*)d_in[3];
    const float* Wkd = (const float*)d_in[4];
    const float* Ukd = (const float*)d_in[5];
    const float* bdv = (const float*)d_in[6];
    const float* Wd  = (const float*)d_in[7];
    const float* bd  = (const float*)d_in[8];
    float* out = (float*)d_out;

    int Bn = in_sizes[0] / T_WARM;   // F == 1
    int grid = (Bn + NTHREADS - 1) / NTHREADS;
    feedback_lstm_kernel<<<grid, NTHREADS>>>(X, Wkw, Ukw, bw, Wkd, Ukd, bdv, Wd, bd, out);
}

// round 3
// speedup vs baseline: 1.5559x; 1.5559x over previous
#include <cuda_runtime.h>

#define T_WARM 48
#define OUT_STEPS 24
#define UNITS 32
#define NTHREADS 128   // 4 warps = 4 batch elements per block

typedef unsigned long long u64;

__device__ __forceinline__ u64 pack2(float lo, float hi) {
    u64 r; asm("mov.b64 %0, {%1, %2};" : "=l"(r) : "f"(lo), "f"(hi)); return r;
}
__device__ __forceinline__ u64 fma2(u64 a, u64 b, u64 c) {
    u64 d; asm("fma.rn.f32x2 %0, %1, %2, %3;" : "=l"(d) : "l"(a), "l"(b), "l"(c)); return d;
}
__device__ __forceinline__ void unpack2(u64 v, float& lo, float& hi) {
    asm("mov.b64 {%0, %1}, %2;" : "=f"(lo), "=f"(hi) : "l"(v));
}
__device__ __forceinline__ float sigmoid_f(float x) {
    return __fdividef(1.f, 1.f + __expf(-x));
}
__device__ __forceinline__ float tanh_f(float x) {
    float ax = fabsf(x);
    float e = __expf(-2.f * ax);
    float r = __fdividef(1.f - e, 1.f + e);
    return copysignf(r, x);
}

// One LSTM cell step for this lane's unit. Weights live in registers.
__device__ __forceinline__ void cell_step(float x,
                                          const u64 (&wif)[32], const u64 (&wgo)[32],
                                          u64 wxif, u64 wxgo, u64 bif, u64 bgo,
                                          float& h, float& c)
{
    u64 xs  = pack2(x, x);
    u64 zif = fma2(xs, wxif, bif);
    u64 zgo = fma2(xs, wxgo, bgo);
    #pragma unroll
    for (int k = 0; k < 32; k++) {
        float hk = __shfl_sync(0xffffffffu, h, k);
        u64 hs = pack2(hk, hk);
        zif = fma2(hs, wif[k], zif);
        zgo = fma2(hs, wgo[k], zgo);
    }
    float zi, zf, zg, zo;
    unpack2(zif, zi, zf);
    unpack2(zgo, zg, zo);
    float ig = sigmoid_f(zi);
    float fg = sigmoid_f(zf);
    float gg = tanh_f(zg);
    float og = sigmoid_f(zo);
    c = fmaf(fg, c, ig * gg);
    h = og * tanh_f(c);
}

__device__ __forceinline__ float warp_proj(float h, float wo, float bo) {
    float v = h * wo;
    v += __shfl_xor_sync(0xffffffffu, v, 16);
    v += __shfl_xor_sync(0xffffffffu, v, 8);
    v += __shfl_xor_sync(0xffffffffu, v, 4);
    v += __shfl_xor_sync(0xffffffffu, v, 2);
    v += __shfl_xor_sync(0xffffffffu, v, 1);
    return v + bo;
}

__global__ void __launch_bounds__(NTHREADS, 3)
feedback_lstm_kernel(const float* __restrict__ X,
                     const float* __restrict__ Wkw, const float* __restrict__ Ukw,
                     const float* __restrict__ bw,
                     const float* __restrict__ Wkd, const float* __restrict__ Ukd,
                     const float* __restrict__ bdv,
                     const float* __restrict__ Wd,  const float* __restrict__ bd,
                     float* __restrict__ out)
{
    // Stage both U matrices in shared once per CTA (row-major, as given:
    // U[k*128 + col]).  Per-thread register loads below are lane-stride-1
    // -> conflict-free, one-time cost.
    __shared__ float sU0[32 * 128];
    __shared__ float sU1[32 * 128];
    __shared__ float sWx0[128], sWx1[128], sB0[128], sB1[128];
    __shared__ float sWo[UNITS];
    __shared__ float sbo;

    const int tid = threadIdx.x;
    #pragma unroll 4
    for (int i = tid; i < 32 * 128; i += NTHREADS) {
        sU0[i] = Ukw[i];
        sU1[i] = Ukd[i];
    }
    if (tid < 128) {
        sWx0[tid] = Wkw[tid];
        sB0[tid]  = bw[tid];
        sWx1[tid] = Wkd[tid];
        sB1[tid]  = bdv[tid];
    }
    if (tid < UNITS) sWo[tid] = Wd[tid];
    if (tid == 0) sbo = bd[0];
    __syncthreads();

    const int lane = tid & 31;
    const int warp = tid >> 5;
    const int b = blockIdx.x * (NTHREADS / 32) + warp;

    // Pre-load this batch's 48 inputs into lane registers (coalesced),
    // redistributed by shfl inside the loop -> no LDG latency per step.
    const float* xrow = X + (size_t)b * T_WARM;
    float xa = xrow[lane];
    float xb = (lane < 16) ? xrow[32 + lane] : 0.f;

    const float wo = sWo[lane];
    const float bo = sbo;

    float h = 0.f, c = 0.f;

    // ---- Phase 1: warmup (48 steps), warm weights in registers ----
    u64 wif[32], wgo[32];
    u64 wxif, wxgo, bif, bgo;
    #pragma unroll
    for (int k = 0; k < 32; k++) {
        wif[k] = pack2(sU0[k * 128 + lane],      sU0[k * 128 + 32 + lane]);
        wgo[k] = pack2(sU0[k * 128 + 64 + lane], sU0[k * 128 + 96 + lane]);
    }
    wxif = pack2(sWx0[lane],      sWx0[32 + lane]);
    wxgo = pack2(sWx0[64 + lane], sWx0[96 + lane]);
    bif  = pack2(sB0[lane],       sB0[32 + lane]);
    bgo  = pack2(sB0[64 + lane],  sB0[96 + lane]);

    for (int t = 0; t < T_WARM; t++) {
        float x = __shfl_sync(0xffffffffu, (t < 32) ? xa : xb, t & 31);
        cell_step(x, wif, wgo, wxif, wxgo, bif, bgo, h, c);
    }

    float p = warp_proj(h, wo, bo);
    float myp = p;   // lane 0 keeps step 0; others overwritten at their step

    // ---- Phase 2: decode (23 steps), reload registers with decode weights ----
    #pragma unroll
    for (int k = 0; k < 32; k++) {
        wif[k] = pack2(sU1[k * 128 + lane],      sU1[k * 128 + 32 + lane]);
        wgo[k] = pack2(sU1[k * 128 + 64 + lane], sU1[k * 128 + 96 + lane]);
    }
    wxif = pack2(sWx1[lane],      sWx1[32 + lane]);
    wxgo = pack2(sWx1[64 + lane], sWx1[96 + lane]);
    bif  = pack2(sB1[lane],       sB1[32 + lane]);
    bgo  = pack2(sB1[64 + lane],  sB1[96 + lane]);

    for (int s = 1; s < OUT_STEPS; s++) {
        cell_step(p, wif, wgo, wxif, wxgo, bif, bgo, h, c);
        p = warp_proj(h, wo, bo);
        if (lane == s) myp = p;
    }

    if (lane < OUT_STEPS) out[(size_t)b * OUT_STEPS + lane] = myp;
}

extern "C" void kernel_launch(void* const* d_in, const int* in_sizes, int n_in,
                              void* d_out, int out_size) {
    const float* X   = (const float*)d_in[0];
    const float* Wkw = (const float*)d_in[1];
    const float* Ukw = (const float*)d_in[2];
    const float* bw  = (const float*)d_in[3];
    const float* Wkd = (const float*)d_in[4];
    const float* Ukd = (const float*)d_in[5];
    const float* bdv = (const float*)d_in[6];
    const float* Wd  = (const float*)d_in[7];
    const float* bd  = (const float*)d_in[8];
    float* out = (float*)d_out;

    int Bn = in_sizes[0] / T_WARM;            // F == 1
    int batches_per_block = NTHREADS / 32;
    int grid = (Bn + batches_per_block - 1) / batches_per_block;
    feedback_lstm_kernel<<<grid, NTHREADS>>>(X, Wkw, Ukw, bw, Wkd, Ukd, bdv, Wd, bd, out);
}